// round 1
// baseline (speedup 1.0000x reference)
#include <cuda_runtime.h>
#include <cstddef>

#define NTHREADS 256
#define TROWS 64   // rows per block

// ---- epilogue chunk maps (31 chunks of 8 output cols after the 64 hand_board cols) ----
// kind 0 = embedding lookup: A = float offset of table in blob, B = state column
// kind 1 = scalar proj:      A = state scal column,            B = scalar_W row index
__constant__ int c_kind[31] = {0,0,0,0,0,0,0,0,0,0,0,0,1,1,1,1,0,0,0,1,0,0,0,0,0,1,1,1,1,1,1};
__constant__ int c_A[31]    = {320,152,304,304,304,304,304,152,152,152,152,152,
                               40,41,42,43, 152,208,416, 39, 208,152,416,360,152,
                               44,45,46,47,48,49};
__constant__ int c_B[31]    = {18,20,22,23,24,25,26,27,28,29,30,31,
                               0,2,3,5, 35,36,37, 1, 32,33,34,19,38,
                               4,4,4,4,4,4};

// blob layout (float offsets): suit@0(40) rank@40(112) pos@152(56) action@208(96)
// active@304(16) street@320(40) numpl@360(56) blind@416(16)  total 432 floats

// shared layout (floats)
#define OFF_SS    0                    // state tile 64*52
#define OFF_BLOB  (OFF_SS + 64*52)     // 432
#define OFF_SW    (OFF_BLOB + 432)     // 48
#define OFF_SB    (OFF_SW + 48)        // 48
#define OFF_S1    (OFF_SB + 48)        // 144*64
#define OFF_S2    (OFF_S1 + 144*64)    // 144*64
#define OFF_WS    (OFF_S2 + 144*64)    // 144*144
#define SMEM_FLOATS (OFF_WS + 144*144)
#define SMEM_BYTES  (SMEM_FLOATS * 4)  // 172096 B

__device__ __forceinline__ float lrelu(float v) { return v > 0.0f ? v : 0.01f * v; }

// One dense layer for a 64-row tile. Xs layout [NIN][64], Ys layout [NOUT][64].
// Thread t computes a 4-row x 4-col micro-tile; j tiled by 64.
template<int NIN, int NOUT, bool ACT>
__device__ __forceinline__ void mlp_layer(const float* __restrict__ Xs,
                                          float* __restrict__ Ys,
                                          const float* __restrict__ Wg,
                                          const float* __restrict__ bg,
                                          float* __restrict__ Ws)
{
    const int t = threadIdx.x;
    for (int i = t * 4; i < NIN * NOUT; i += NTHREADS * 4)
        *reinterpret_cast<float4*>(Ws + i) = *reinterpret_cast<const float4*>(Wg + i);
    __syncthreads();

    const int rq  = (t & 15) << 2;   // row base 0..60
    const int jqb = (t >> 4) << 2;   // col base 0..60

    for (int j0 = jqb; j0 < NOUT; j0 += 64) {
        float acc[4][4] = {};
        #pragma unroll 8
        for (int k = 0; k < NIN; k++) {
            float4 x = *reinterpret_cast<const float4*>(Xs + k * TROWS + rq);
            float4 w = *reinterpret_cast<const float4*>(Ws + k * NOUT + j0);
            float xr[4] = {x.x, x.y, x.z, x.w};
            float wj[4] = {w.x, w.y, w.z, w.w};
            #pragma unroll
            for (int jj = 0; jj < 4; jj++)
                #pragma unroll
                for (int rr = 0; rr < 4; rr++)
                    acc[jj][rr] += xr[rr] * wj[jj];
        }
        float4 b4 = *reinterpret_cast<const float4*>(bg + j0);
        float bb[4] = {b4.x, b4.y, b4.z, b4.w};
        #pragma unroll
        for (int jj = 0; jj < 4; jj++) {
            float4 o;
            o.x = acc[jj][0] + bb[jj];
            o.y = acc[jj][1] + bb[jj];
            o.z = acc[jj][2] + bb[jj];
            o.w = acc[jj][3] + bb[jj];
            if (ACT) { o.x = lrelu(o.x); o.y = lrelu(o.y); o.z = lrelu(o.z); o.w = lrelu(o.w); }
            *reinterpret_cast<float4*>(Ys + (j0 + jj) * TROWS + rq) = o;
        }
    }
    __syncthreads();
}

// Final layer (NOUT=64, no activation): writes directly to global out, cols [0,64)
template<int NIN>
__device__ __forceinline__ void mlp_final(const float* __restrict__ Xs,
                                          const float* __restrict__ Wg,
                                          const float* __restrict__ bg,
                                          float* __restrict__ Ws,
                                          float* __restrict__ out,
                                          size_t g0)
{
    const int t = threadIdx.x;
    for (int i = t * 4; i < NIN * 64; i += NTHREADS * 4)
        *reinterpret_cast<float4*>(Ws + i) = *reinterpret_cast<const float4*>(Wg + i);
    __syncthreads();

    const int rq = (t & 15) << 2;
    const int j0 = (t >> 4) << 2;

    float acc[4][4] = {};
    #pragma unroll 8
    for (int k = 0; k < NIN; k++) {
        float4 x = *reinterpret_cast<const float4*>(Xs + k * TROWS + rq);
        float4 w = *reinterpret_cast<const float4*>(Ws + k * 64 + j0);
        float xr[4] = {x.x, x.y, x.z, x.w};
        float wj[4] = {w.x, w.y, w.z, w.w};
        #pragma unroll
        for (int jj = 0; jj < 4; jj++)
            #pragma unroll
            for (int rr = 0; rr < 4; rr++)
                acc[jj][rr] += xr[rr] * wj[jj];
    }
    float4 b4 = *reinterpret_cast<const float4*>(bg + j0);
    #pragma unroll
    for (int rr = 0; rr < 4; rr++) {
        float4 o;
        o.x = acc[0][rr] + b4.x;
        o.y = acc[1][rr] + b4.y;
        o.z = acc[2][rr] + b4.z;
        o.w = acc[3][rr] + b4.w;
        *reinterpret_cast<float4*>(out + (g0 + rq + rr) * 312 + j0) = o;
    }
}

__global__ void __launch_bounds__(NTHREADS, 1)
preproc_kernel(const float* __restrict__ state,
               const float* __restrict__ suit_emb, const float* __restrict__ rank_emb,
               const float* __restrict__ hW1, const float* __restrict__ hb1,
               const float* __restrict__ hW2, const float* __restrict__ hb2,
               const float* __restrict__ hW3, const float* __restrict__ hb3,
               const float* __restrict__ bW1, const float* __restrict__ bb1,
               const float* __restrict__ bW2, const float* __restrict__ bb2,
               const float* __restrict__ bW3, const float* __restrict__ bb3,
               const float* __restrict__ cW1, const float* __restrict__ cb1,
               const float* __restrict__ cW2, const float* __restrict__ cb2,
               const float* __restrict__ cW3, const float* __restrict__ cb3,
               const float* __restrict__ pos_emb, const float* __restrict__ action_emb,
               const float* __restrict__ active_emb, const float* __restrict__ street_emb,
               const float* __restrict__ numpl_emb, const float* __restrict__ blind_emb,
               const float* __restrict__ scalar_W, const float* __restrict__ scalar_b,
               float* __restrict__ out)
{
    extern __shared__ float smem[];
    float* Ss   = smem + OFF_SS;
    float* blob = smem + OFF_BLOB;
    float* sW   = smem + OFF_SW;
    float* sB   = smem + OFF_SB;
    float* S1   = smem + OFF_S1;
    float* S2   = smem + OFF_S2;
    float* Ws   = smem + OFF_WS;

    const int t = threadIdx.x;
    const size_t g0 = (size_t)blockIdx.x * TROWS;

    // ---- load state tile (64 rows x 50 cols, padded stride 52) ----
    const float* sp = state + g0 * 50;
    for (int i = t; i < TROWS * 50; i += NTHREADS) {
        int r = i / 50, c = i - r * 50;
        Ss[r * 52 + c] = sp[i];
    }
    // ---- load embedding tables into blob ----
    for (int i = t; i < 40;  i += NTHREADS) blob[0   + i] = suit_emb[i];
    for (int i = t; i < 112; i += NTHREADS) blob[40  + i] = rank_emb[i];
    for (int i = t; i < 56;  i += NTHREADS) blob[152 + i] = pos_emb[i];
    for (int i = t; i < 96;  i += NTHREADS) blob[208 + i] = action_emb[i];
    for (int i = t; i < 16;  i += NTHREADS) blob[304 + i] = active_emb[i];
    for (int i = t; i < 40;  i += NTHREADS) blob[320 + i] = street_emb[i];
    for (int i = t; i < 56;  i += NTHREADS) blob[360 + i] = numpl_emb[i];
    for (int i = t; i < 16;  i += NTHREADS) blob[416 + i] = blind_emb[i];
    for (int i = t; i < 48;  i += NTHREADS) { sW[i] = scalar_W[i]; sB[i] = scalar_b[i]; }
    __syncthreads();

    // ---- cheap output columns 64..311 ----
    for (int i = t; i < TROWS * 248; i += NTHREADS) {
        int r = i / 248, cc = i - r * 248;
        int ch = cc >> 3, e = cc & 7;
        int kind = c_kind[ch], A = c_A[ch], Bc = c_B[ch];
        float v;
        if (kind == 0) {
            int xi = (int)Ss[r * 52 + Bc];
            v = blob[A + xi * 8 + e];
        } else {
            v = Ss[r * 52 + A] * sW[Bc * 8 + e] + sB[Bc * 8 + e];
        }
        out[(g0 + r) * 312 + 64 + cc] = v;
    }

    // ---- gather hand input (64 feats) into S1 [k][row] ----
    for (int i = t; i < 64 * TROWS; i += NTHREADS) {
        int r = i & 63, k = i >> 6;
        int c = k >> 4, w = k & 15;
        float v;
        if (w < 8) { int s  = (int)Ss[r * 52 + 2 * c + 1]; v = blob[0  + s * 8 + w]; }
        else       { int rk = (int)Ss[r * 52 + 2 * c];     v = blob[40 + rk * 8 + (w - 8)]; }
        S1[k * TROWS + r] = v;
    }
    __syncthreads();

    mlp_layer<64, 64, true >(S1, S2, hW1, hb1, Ws);
    mlp_layer<64, 64, true >(S2, S1, hW2, hb2, Ws);
    mlp_layer<64, 64, false>(S1, S2, hW3, hb3, Ws);   // hand out -> S2 rows [0,64)

    // ---- gather board input (80 feats) into S1 [k][row] ----
    for (int i = t; i < 80 * TROWS; i += NTHREADS) {
        int r = i & 63, k = i >> 6;
        int c = k >> 4, w = k & 15;
        float v;
        if (w < 8) { int s  = (int)Ss[r * 52 + 9 + 2 * c]; v = blob[0  + s * 8 + w]; }
        else       { int rk = (int)Ss[r * 52 + 8 + 2 * c]; v = blob[40 + rk * 8 + (w - 8)]; }
        S1[k * TROWS + r] = v;
    }
    __syncthreads();

    mlp_layer<80, 80, true >(S1, S2 + 64 * TROWS, bW1, bb1, Ws);
    mlp_layer<80, 80, true >(S2 + 64 * TROWS, S1, bW2, bb2, Ws);
    mlp_layer<80, 80, false>(S1, S2 + 64 * TROWS, bW3, bb3, Ws);  // board out -> S2 rows [64,144)

    // ---- combined MLP: S2 holds [hand(64); board(80)] ----
    mlp_layer<144, 144, true>(S2, S1, cW1, cb1, Ws);
    mlp_layer<144, 64,  true>(S1, S2, cW2, cb2, Ws);
    mlp_final<64>(S2, cW3, cb3, Ws, out, g0);
}

extern "C" void kernel_launch(void* const* d_in, const int* in_sizes, int n_in,
                              void* d_out, int out_size)
{
    (void)n_in; (void)out_size;
    cudaFuncSetAttribute(preproc_kernel, cudaFuncAttributeMaxDynamicSharedMemorySize, SMEM_BYTES);

    const int nrows = in_sizes[0] / 50;     // 262144
    const int grid  = nrows / TROWS;        // 4096

    preproc_kernel<<<grid, NTHREADS, SMEM_BYTES>>>(
        (const float*)d_in[0],
        (const float*)d_in[1],  (const float*)d_in[2],
        (const float*)d_in[3],  (const float*)d_in[4],
        (const float*)d_in[5],  (const float*)d_in[6],
        (const float*)d_in[7],  (const float*)d_in[8],
        (const float*)d_in[9],  (const float*)d_in[10],
        (const float*)d_in[11], (const float*)d_in[12],
        (const float*)d_in[13], (const float*)d_in[14],
        (const float*)d_in[15], (const float*)d_in[16],
        (const float*)d_in[17], (const float*)d_in[18],
        (const float*)d_in[19], (const float*)d_in[20],
        (const float*)d_in[21], (const float*)d_in[22],
        (const float*)d_in[23], (const float*)d_in[24],
        (const float*)d_in[25], (const float*)d_in[26],
        (const float*)d_in[27], (const float*)d_in[28],
        (float*)d_out);
}